// round 3
// baseline (speedup 1.0000x reference)
#include <cuda_runtime.h>
#include <math.h>

#define BS     32
#define GRID_N 2704
#define A_N    3
#define CH     85
#define VDIM   1024
#define HDIM   512
#define SEL    32
#define EPSF   1e-8f

// ---------------- device scratch (static, no allocation) ----------------
__device__ int   g_idx[BS * SEL];
__device__ float g_isel[(size_t)BS * SEL * VDIM];
__device__ float g_vis[(size_t)BS * SEL * HDIM];
__device__ float g_w[BS * SEL * 2];
__device__ float g_vis2[(size_t)BS * SEL * HDIM];
__device__ float g_lang[BS * HDIM];
__device__ float g_ln[BS];

// ---------------- K1: objectness score + exact top-32 via histogram ------
__global__ void topk_kernel(const float* __restrict__ boxes) {
    int b = blockIdx.x;
    int tid = threadIdx.x;          // 256 threads
    __shared__ float sc[GRID_N];
    __shared__ int   hist[512];
    __shared__ int   s_binB, s_definite;
    __shared__ int   cnt_hi, cnt_cb, overflow;
    __shared__ int   hi_idx[SEL];
    __shared__ float cb_sc[512];
    __shared__ int   cb_idx[512];
    __shared__ int   sel[SEL];
    __shared__ float rv[8];
    __shared__ int   ri[8];

    for (int i = tid; i < 512; i += 256) hist[i] = 0;
    if (tid == 0) { cnt_hi = 0; cnt_cb = 0; overflow = 0; }
    __syncthreads();

    const float* bb = boxes + (size_t)b * GRID_N * A_N * CH;
    for (int g = tid; g < GRID_N; g += 256) {
        const float* p = bb + (size_t)g * A_N * CH;
        float s = (p[4] + p[CH + 4] + p[2 * CH + 4]) * (1.0f / 3.0f);
        sc[g] = s;
        int bin = (int)(s * 512.0f);
        bin = max(0, min(511, bin));
        atomicAdd(&hist[bin], 1);
    }
    __syncthreads();

    if (tid == 0) {
        int cum = 0, bB = 0, def = 0;
        for (int v = 511; v >= 0; v--) {
            cum += hist[v];
            if (cum >= SEL) { bB = v; def = cum - hist[v]; break; }
        }
        s_binB = bB; s_definite = def;
    }
    __syncthreads();
    int binB = s_binB;

    for (int g = tid; g < GRID_N; g += 256) {
        float s = sc[g];
        int bin = (int)(s * 512.0f);
        bin = max(0, min(511, bin));
        if (bin > binB) {
            int p = atomicAdd(&cnt_hi, 1);
            hi_idx[p] = g;                      // p < SEL guaranteed
        } else if (bin == binB) {
            int p = atomicAdd(&cnt_cb, 1);
            if (p < 512) { cb_sc[p] = s; cb_idx[p] = g; }
            else overflow = 1;
        }
    }
    __syncthreads();

    if (!overflow) {
        // threads 32..: copy definite winners
        if (tid >= 32 && (tid - 32) < s_definite) sel[tid - 32] = hi_idx[tid - 32];
        // warp 0: select remaining from critical bin (value desc, index asc tiebreak)
        if (tid < 32) {
            int need = SEL - s_definite;
            int n = min(cnt_cb, 512);
            for (int it = 0; it < need; it++) {
                float best = -1e30f; int bi = GRID_N;
                for (int c = tid; c < n; c += 32) {
                    float v = cb_sc[c]; int gi = cb_idx[c];
                    if (v > best || (v == best && gi < bi)) { best = v; bi = gi; }
                }
                #pragma unroll
                for (int o = 16; o; o >>= 1) {
                    float ov = __shfl_down_sync(0xffffffffu, best, o);
                    int   oi = __shfl_down_sync(0xffffffffu, bi, o);
                    if (ov > best || (ov == best && oi < bi)) { best = ov; bi = oi; }
                }
                bi = __shfl_sync(0xffffffffu, bi, 0);
                if (tid == 0) sel[s_definite + it] = bi;
                for (int c = tid; c < n; c += 32)
                    if (cb_idx[c] == bi) cb_sc[c] = -1e30f;
                __syncwarp();
            }
        }
    }
    __syncthreads();

    if (overflow) {
        // exact fallback: iterative extraction (rare, degenerate distributions)
        for (int it = 0; it < SEL; it++) {
            float best = -1e30f;
            int   bi = GRID_N;
            for (int g = tid; g < GRID_N; g += 256) {
                float v = sc[g];
                if (v > best) { best = v; bi = g; }
            }
            #pragma unroll
            for (int o = 16; o; o >>= 1) {
                float ov = __shfl_down_sync(0xffffffffu, best, o);
                int   oi = __shfl_down_sync(0xffffffffu, bi, o);
                if (ov > best || (ov == best && oi < bi)) { best = ov; bi = oi; }
            }
            if ((tid & 31) == 0) { rv[tid >> 5] = best; ri[tid >> 5] = bi; }
            __syncthreads();
            if (tid == 0) {
                float B = rv[0]; int BI = ri[0];
                for (int w = 1; w < 8; w++)
                    if (rv[w] > B || (rv[w] == B && ri[w] < BI)) { B = rv[w]; BI = ri[w]; }
                sel[it] = BI;
                sc[BI] = -1e30f;
            }
            __syncthreads();
        }
    }

    if (tid == 0) {
        for (int i = 1; i < SEL; i++) {          // ascending index sort
            int v = sel[i], j = i - 1;
            while (j >= 0 && sel[j] > v) { sel[j + 1] = sel[j]; j--; }
            sel[j + 1] = v;
        }
        for (int i = 0; i < SEL; i++) g_idx[b * SEL + i] = sel[i];
    }
}

// ---------------- K2: gather selected feature columns --------------------
__global__ void gather_kernel(const float* __restrict__ xfeat) {
    int row = blockIdx.x;           // b*SEL + s
    int b = row >> 5;
    int g = g_idx[row];
    const float* src = xfeat + (size_t)b * VDIM * GRID_N + g;
    float* dst = g_isel + (size_t)row * VDIM;
    for (int v = threadIdx.x; v < VDIM; v += blockDim.x)
        dst[v] = __ldg(&src[(size_t)v * GRID_N]);
}

// ---------------- K3: vis = i_sel @ W_vs + b_vs (double buffered) --------
#define KT1 32
#define NT1 (VDIM / KT1)
__global__ __launch_bounds__(128) void gemm1_kernel(const float* __restrict__ W,
                                                    const float* __restrict__ bias) {
    int b = blockIdx.y;
    int nb = blockIdx.x * 64;
    int tid = threadIdx.x;
    int tx = tid & 15, ty = tid >> 4;

    __shared__ float Xs[2][KT1 * 33];
    __shared__ __align__(16) float Ws[2][KT1 * 64];

    const float* Ab = g_isel + (size_t)b * SEL * VDIM;

    // load addressing
    int wk = tid >> 4;             // W: k = wk + i*8,  n = wn..wn+3
    int wn = (tid * 4) & 63;
    int xm = tid >> 3;             // X: m = xm + i*16, k = xk..xk+3
    int xk = (tid * 4) & 31;

    float4 rW[4], rX[2];

    // prologue: tile 0
    #pragma unroll
    for (int i = 0; i < 4; i++)
        rW[i] = *(const float4*)&W[(size_t)(wk + i * 8) * HDIM + nb + wn];
    #pragma unroll
    for (int i = 0; i < 2; i++)
        rX[i] = *(const float4*)&Ab[(size_t)(xm + i * 16) * VDIM + xk];
    #pragma unroll
    for (int i = 0; i < 4; i++)
        *(float4*)&Ws[0][(wk + i * 8) * 64 + wn] = rW[i];
    #pragma unroll
    for (int i = 0; i < 2; i++) {
        int m = xm + i * 16;
        Xs[0][(xk + 0) * 33 + m] = rX[i].x;
        Xs[0][(xk + 1) * 33 + m] = rX[i].y;
        Xs[0][(xk + 2) * 33 + m] = rX[i].z;
        Xs[0][(xk + 3) * 33 + m] = rX[i].w;
    }
    __syncthreads();

    float acc[4][4];
    #pragma unroll
    for (int i = 0; i < 4; i++)
        #pragma unroll
        for (int j = 0; j < 4; j++) acc[i][j] = 0.f;

    for (int t = 0; t < NT1; t++) {
        int cur = t & 1;
        int k0n = (t + 1) * KT1;
        if (t + 1 < NT1) {
            #pragma unroll
            for (int i = 0; i < 4; i++)
                rW[i] = *(const float4*)&W[(size_t)(k0n + wk + i * 8) * HDIM + nb + wn];
            #pragma unroll
            for (int i = 0; i < 2; i++)
                rX[i] = *(const float4*)&Ab[(size_t)(xm + i * 16) * VDIM + k0n + xk];
        }
        #pragma unroll
        for (int k = 0; k < KT1; k++) {
            float4 wv = *(const float4*)&Ws[cur][k * 64 + tx * 4];
            float x0 = Xs[cur][k * 33 + ty * 4 + 0];
            float x1 = Xs[cur][k * 33 + ty * 4 + 1];
            float x2 = Xs[cur][k * 33 + ty * 4 + 2];
            float x3 = Xs[cur][k * 33 + ty * 4 + 3];
            acc[0][0] += x0 * wv.x; acc[0][1] += x0 * wv.y; acc[0][2] += x0 * wv.z; acc[0][3] += x0 * wv.w;
            acc[1][0] += x1 * wv.x; acc[1][1] += x1 * wv.y; acc[1][2] += x1 * wv.z; acc[1][3] += x1 * wv.w;
            acc[2][0] += x2 * wv.x; acc[2][1] += x2 * wv.y; acc[2][2] += x2 * wv.z; acc[2][3] += x2 * wv.w;
            acc[3][0] += x3 * wv.x; acc[3][1] += x3 * wv.y; acc[3][2] += x3 * wv.z; acc[3][3] += x3 * wv.w;
        }
        if (t + 1 < NT1) {
            int nx = cur ^ 1;
            #pragma unroll
            for (int i = 0; i < 4; i++)
                *(float4*)&Ws[nx][(wk + i * 8) * 64 + wn] = rW[i];
            #pragma unroll
            for (int i = 0; i < 2; i++) {
                int m = xm + i * 16;
                Xs[nx][(xk + 0) * 33 + m] = rX[i].x;
                Xs[nx][(xk + 1) * 33 + m] = rX[i].y;
                Xs[nx][(xk + 2) * 33 + m] = rX[i].z;
                Xs[nx][(xk + 3) * 33 + m] = rX[i].w;
            }
        }
        __syncthreads();
    }

    #pragma unroll
    for (int i = 0; i < 4; i++) {
        int m = ty * 4 + i;
        float* C = g_vis + (size_t)(b * SEL + m) * HDIM + nb;
        #pragma unroll
        for (int j = 0; j < 4; j++)
            C[tx * 4 + j] = acc[i][j] + bias[nb + tx * 4 + j];
    }
}

// ---------------- K4: gate logits -> log_softmax weights (float4) --------
__global__ void wsoft_kernel(const float* __restrict__ tag, const float* __restrict__ pos,
                             const float* __restrict__ Wsoft, const float* __restrict__ bsoft) {
    int warp = (blockIdx.x * blockDim.x + threadIdx.x) >> 5;
    int lane = threadIdx.x & 31;
    if (warp >= BS * SEL) return;
    const float4* v = (const float4*)(g_vis + (size_t)warp * HDIM);
    const float4* t = (const float4*)(tag + (size_t)warp * HDIM);
    const float4* p = (const float4*)(pos + (size_t)warp * HDIM);
    const float4* Wq = (const float4*)Wsoft;   // [h][2] pairs, float4 = 2 h-rows
    float l0 = 0.f, l1 = 0.f;
    #pragma unroll
    for (int i = 0; i < 4; i++) {
        int h4 = lane + i * 32;
        float4 a = v[h4], c = t[h4], e = p[h4];
        float s0 = a.x + c.x + e.x, s1 = a.y + c.y + e.y;
        float s2 = a.z + c.z + e.z, s3 = a.w + c.w + e.w;
        float4 w01 = Wq[h4 * 2], w23 = Wq[h4 * 2 + 1];
        l0 += s0 * w01.x + s1 * w01.z + s2 * w23.x + s3 * w23.z;
        l1 += s0 * w01.y + s1 * w01.w + s2 * w23.y + s3 * w23.w;
    }
    #pragma unroll
    for (int o = 16; o; o >>= 1) {
        l0 += __shfl_xor_sync(0xffffffffu, l0, o);
        l1 += __shfl_xor_sync(0xffffffffu, l1, o);
    }
    if (lane == 0) {
        l0 = (l0 + bsoft[0]) / 0.03f;
        l1 = (l1 + bsoft[1]) / 0.03f;
        float m = fmaxf(l0, l1);
        float lse = m + logf(expf(l0 - m) + expf(l1 - m));
        g_w[2 * warp + 0] = l0 - lse;
        g_w[2 * warp + 1] = l1 - lse;
    }
}

// ---------------- K5: vis2 GEMM (double buffered, KT=16) -----------------
#define KT2 16
#define NT2 (HDIM / KT2)
__global__ __launch_bounds__(128) void gemm2_kernel(
    const float* __restrict__ Wvp, const float* __restrict__ bvp,
    const float* __restrict__ Wtg, const float* __restrict__ btg,
    const float* __restrict__ tag, const float* __restrict__ pos) {
    int b = blockIdx.y;
    int nb = blockIdx.x * 64;
    int tid = threadIdx.x;
    int tx = tid & 15, ty = tid >> 4;

    __shared__ float Xs[2][KT2 * 35], Ys[2][KT2 * 35];
    __shared__ __align__(16) float Ws[2][KT2 * 64];
    __shared__ __align__(16) float Vs[2][KT2 * 64];
    __shared__ float w0s[SEL], w1s[SEL];

    if (tid < SEL) {
        w0s[tid] = g_w[(b * SEL + tid) * 2 + 0];
        w1s[tid] = g_w[(b * SEL + tid) * 2 + 1];
    }
    __syncthreads();

    const float* Vb = g_vis + (size_t)b * SEL * HDIM;
    const float* Tb = tag + (size_t)b * SEL * HDIM;

    int wk = tid >> 4;             // W/V: k = wk + i*8 (i=0..1), n = wn..+3
    int wn = (tid * 4) & 63;
    int xm = tid >> 2;             // X/Y: m = xm, k = xk..+3
    int xk = (tid * 4) & 15;
    float fw0 = w0s[xm], fw1 = w1s[xm];

    float4 rW[2], rV[2], rX, rY;

    // prologue
    #pragma unroll
    for (int i = 0; i < 2; i++) {
        rW[i] = *(const float4*)&Wvp[(size_t)(wk + i * 8) * HDIM + nb + wn];
        rV[i] = *(const float4*)&Wtg[(size_t)(wk + i * 8) * HDIM + nb + wn];
    }
    rX = *(const float4*)&Vb[(size_t)xm * HDIM + xk];
    rY = *(const float4*)&Tb[(size_t)xm * HDIM + xk];
    #pragma unroll
    for (int i = 0; i < 2; i++) {
        *(float4*)&Ws[0][(wk + i * 8) * 64 + wn] = rW[i];
        *(float4*)&Vs[0][(wk + i * 8) * 64 + wn] = rV[i];
    }
    Xs[0][(xk + 0) * 35 + xm] = rX.x * fw0; Xs[0][(xk + 1) * 35 + xm] = rX.y * fw0;
    Xs[0][(xk + 2) * 35 + xm] = rX.z * fw0; Xs[0][(xk + 3) * 35 + xm] = rX.w * fw0;
    Ys[0][(xk + 0) * 35 + xm] = rY.x * fw1; Ys[0][(xk + 1) * 35 + xm] = rY.y * fw1;
    Ys[0][(xk + 2) * 35 + xm] = rY.z * fw1; Ys[0][(xk + 3) * 35 + xm] = rY.w * fw1;
    __syncthreads();

    float acc[4][4];
    #pragma unroll
    for (int i = 0; i < 4; i++)
        #pragma unroll
        for (int j = 0; j < 4; j++) acc[i][j] = 0.f;

    for (int t = 0; t < NT2; t++) {
        int cur = t & 1;
        int k0n = (t + 1) * KT2;
        if (t + 1 < NT2) {
            #pragma unroll
            for (int i = 0; i < 2; i++) {
                rW[i] = *(const float4*)&Wvp[(size_t)(k0n + wk + i * 8) * HDIM + nb + wn];
                rV[i] = *(const float4*)&Wtg[(size_t)(k0n + wk + i * 8) * HDIM + nb + wn];
            }
            rX = *(const float4*)&Vb[(size_t)xm * HDIM + k0n + xk];
            rY = *(const float4*)&Tb[(size_t)xm * HDIM + k0n + xk];
        }
        #pragma unroll
        for (int k = 0; k < KT2; k++) {
            float4 wv = *(const float4*)&Ws[cur][k * 64 + tx * 4];
            float4 vv = *(const float4*)&Vs[cur][k * 64 + tx * 4];
            float x0 = Xs[cur][k * 35 + ty * 4 + 0];
            float x1 = Xs[cur][k * 35 + ty * 4 + 1];
            float x2 = Xs[cur][k * 35 + ty * 4 + 2];
            float x3 = Xs[cur][k * 35 + ty * 4 + 3];
            float y0 = Ys[cur][k * 35 + ty * 4 + 0];
            float y1 = Ys[cur][k * 35 + ty * 4 + 1];
            float y2 = Ys[cur][k * 35 + ty * 4 + 2];
            float y3 = Ys[cur][k * 35 + ty * 4 + 3];
            acc[0][0] += x0 * wv.x + y0 * vv.x; acc[0][1] += x0 * wv.y + y0 * vv.y;
            acc[0][2] += x0 * wv.z + y0 * vv.z; acc[0][3] += x0 * wv.w + y0 * vv.w;
            acc[1][0] += x1 * wv.x + y1 * vv.x; acc[1][1] += x1 * wv.y + y1 * vv.y;
            acc[1][2] += x1 * wv.z + y1 * vv.z; acc[1][3] += x1 * wv.w + y1 * vv.w;
            acc[2][0] += x2 * wv.x + y2 * vv.x; acc[2][1] += x2 * wv.y + y2 * vv.y;
            acc[2][2] += x2 * wv.z + y2 * vv.z; acc[2][3] += x2 * wv.w + y2 * vv.w;
            acc[3][0] += x3 * wv.x + y3 * vv.x; acc[3][1] += x3 * wv.y + y3 * vv.y;
            acc[3][2] += x3 * wv.z + y3 * vv.z; acc[3][3] += x3 * wv.w + y3 * vv.w;
        }
        if (t + 1 < NT2) {
            int nx = cur ^ 1;
            #pragma unroll
            for (int i = 0; i < 2; i++) {
                *(float4*)&Ws[nx][(wk + i * 8) * 64 + wn] = rW[i];
                *(float4*)&Vs[nx][(wk + i * 8) * 64 + wn] = rV[i];
            }
            Xs[nx][(xk + 0) * 35 + xm] = rX.x * fw0; Xs[nx][(xk + 1) * 35 + xm] = rX.y * fw0;
            Xs[nx][(xk + 2) * 35 + xm] = rX.z * fw0; Xs[nx][(xk + 3) * 35 + xm] = rX.w * fw0;
            Ys[nx][(xk + 0) * 35 + xm] = rY.x * fw1; Ys[nx][(xk + 1) * 35 + xm] = rY.y * fw1;
            Ys[nx][(xk + 2) * 35 + xm] = rY.z * fw1; Ys[nx][(xk + 3) * 35 + xm] = rY.w * fw1;
        }
        __syncthreads();
    }

    #pragma unroll
    for (int i = 0; i < 4; i++) {
        int m = ty * 4 + i;
        size_t roff = (size_t)(b * SEL + m) * HDIM + nb;
        #pragma unroll
        for (int j = 0; j < 4; j++) {
            int n = tx * 4 + j;
            g_vis2[roff + n] = acc[i][j] + bvp[nb + n] + btg[nb + n] + pos[roff + n];
        }
    }
}

// ---------------- K6: language projection + norm -------------------------
__global__ void lang_kernel(const float* __restrict__ lang, const float* __restrict__ Wts,
                            const float* __restrict__ bts) {
    int b = blockIdx.x, tid = threadIdx.x;   // 256 threads
    __shared__ float lg[HDIM];
    __shared__ float red[256];
    for (int h = tid; h < HDIM; h += 256) lg[h] = lang[b * HDIM + h];
    __syncthreads();
    int h0 = tid, h1 = tid + 256;
    float a0 = bts[h0], a1 = bts[h1];
    #pragma unroll 4
    for (int k = 0; k < HDIM; k++) {
        float l = lg[k];
        a0 += l * Wts[(size_t)k * HDIM + h0];
        a1 += l * Wts[(size_t)k * HDIM + h1];
    }
    g_lang[b * HDIM + h0] = a0;
    g_lang[b * HDIM + h1] = a1;
    red[tid] = a0 * a0 + a1 * a1;
    __syncthreads();
    for (int o = 128; o; o >>= 1) { if (tid < o) red[tid] += red[tid + o]; __syncthreads(); }
    if (tid == 0) g_ln[b] = sqrtf(red[0]) + EPSF;
}

// ---------------- K7: cosine sim (warp per sel), argmax, box decode ------
__global__ void final_kernel(const float* __restrict__ boxes, float* __restrict__ out) {
    int b = blockIdx.x, tid = threadIdx.x;   // 1024 threads = 32 warps
    int w = tid >> 5, lane = tid & 31;
    __shared__ float ssim[SEL];

    const float4* v2 = (const float4*)(g_vis2 + (size_t)(b * SEL + w) * HDIM);
    const float4* le = (const float4*)(g_lang + (size_t)b * HDIM);
    float d = 0.f, q = 0.f;
    #pragma unroll
    for (int i = 0; i < 4; i++) {
        float4 a = v2[lane + i * 32];
        float4 c = le[lane + i * 32];
        d += a.x * c.x + a.y * c.y + a.z * c.z + a.w * c.w;
        q += a.x * a.x + a.y * a.y + a.z * a.z + a.w * a.w;
    }
    #pragma unroll
    for (int o = 16; o; o >>= 1) {
        d += __shfl_xor_sync(0xffffffffu, d, o);
        q += __shfl_xor_sync(0xffffffffu, q, o);
    }
    if (lane == 0) ssim[w] = d / ((sqrtf(q) + EPSF) * g_ln[b]);
    __syncthreads();

    if (tid < SEL) out[BS * 5 + b * SEL + tid] = ssim[tid];

    if (w == 0) {
        float v = ssim[lane]; int bi = lane;
        #pragma unroll
        for (int o = 16; o; o >>= 1) {
            float ov = __shfl_down_sync(0xffffffffu, v, o);
            int   oi = __shfl_down_sync(0xffffffffu, bi, o);
            if (ov > v || (ov == v && oi < bi)) { v = ov; bi = oi; }
        }
        if (lane == 0) {
            int g = g_idx[b * SEL + bi];
            const float* base = boxes + ((size_t)b * GRID_N + g) * A_N * CH;
            int j = 0; float ov = base[4];
            for (int a = 1; a < A_N; a++) {
                float o2 = base[a * CH + 4];
                if (o2 > ov) { ov = o2; j = a; }
            }
            float x = base[j * CH + 0], y = base[j * CH + 1];
            float wd = base[j * CH + 2], hh = base[j * CH + 3];
            float x1 = x - wd * 0.5f, y1 = y - hh * 0.5f;
            out[b * 5 + 0] = x1;
            out[b * 5 + 1] = y1;
            out[b * 5 + 2] = x1 + wd;
            out[b * 5 + 3] = y1 + hh;
            out[b * 5 + 4] = ov;
        }
    }
}

// ---------------- launch --------------------------------------------------
extern "C" void kernel_launch(void* const* d_in, const int* in_sizes, int n_in,
                              void* d_out, int out_size) {
    const float* boxes    = (const float*)d_in[0];
    const float* x_feat   = (const float*)d_in[1];
    const float* tag_emb  = (const float*)d_in[2];
    const float* pos_emb  = (const float*)d_in[3];
    const float* lang     = (const float*)d_in[4];
    const float* W_vs     = (const float*)d_in[5];
    const float* b_vs     = (const float*)d_in[6];
    const float* W_ts     = (const float*)d_in[7];
    const float* b_ts     = (const float*)d_in[8];
    const float* W_vs_pos = (const float*)d_in[9];
    const float* b_vs_pos = (const float*)d_in[10];
    const float* W_tag    = (const float*)d_in[11];
    const float* b_tag    = (const float*)d_in[12];
    const float* W_soft   = (const float*)d_in[13];
    const float* b_soft   = (const float*)d_in[14];
    float* out = (float*)d_out;

    topk_kernel<<<BS, 256>>>(boxes);
    gather_kernel<<<BS * SEL, 256>>>(x_feat);
    lang_kernel<<<BS, 256>>>(lang, W_ts, b_ts);
    gemm1_kernel<<<dim3(HDIM / 64, BS), 128>>>(W_vs, b_vs);
    wsoft_kernel<<<(BS * SEL * 32 + 255) / 256, 256>>>(tag_emb, pos_emb, W_soft, b_soft);
    gemm2_kernel<<<dim3(HDIM / 64, BS), 128>>>(W_vs_pos, b_vs_pos, W_tag, b_tag, tag_emb, pos_emb);
    final_kernel<<<BS, 1024>>>(boxes, out);
}

// round 4
// speedup vs baseline: 1.0027x; 1.0027x over previous
#include <cuda_runtime.h>
#include <math.h>

#define BS     32
#define GRID_N 2704
#define A_N    3
#define CH     85
#define VDIM   1024
#define HDIM   512
#define SEL    32
#define EPSF   1e-8f

// ---------------- device scratch (static, no allocation) ----------------
__device__ int   g_idx[BS * SEL];
__device__ float g_isel[(size_t)BS * SEL * VDIM];
__device__ float g_vis[(size_t)BS * SEL * HDIM];
__device__ float g_w[BS * SEL * 2];
__device__ float g_vis2[(size_t)BS * SEL * HDIM];
__device__ float g_lang[BS * HDIM];
__device__ float g_ln[BS];

// ---------------- K1: objectness score + exact top-32 via histogram ------
__global__ void topk_kernel(const float* __restrict__ boxes) {
    int b = blockIdx.x;
    int tid = threadIdx.x;          // 256 threads
    __shared__ float sc[GRID_N];
    __shared__ int   hist[512];
    __shared__ int   s_binB, s_definite;
    __shared__ int   cnt_hi, cnt_cb, overflow;
    __shared__ int   hi_idx[SEL];
    __shared__ float cb_sc[512];
    __shared__ int   cb_idx[512];
    __shared__ int   sel[SEL];
    __shared__ float rv[8];
    __shared__ int   ri[8];

    for (int i = tid; i < 512; i += 256) hist[i] = 0;
    if (tid == 0) { cnt_hi = 0; cnt_cb = 0; overflow = 0; }
    __syncthreads();

    const float* bb = boxes + (size_t)b * GRID_N * A_N * CH;
    for (int g = tid; g < GRID_N; g += 256) {
        const float* p = bb + (size_t)g * A_N * CH;
        float s = (p[4] + p[CH + 4] + p[2 * CH + 4]) * (1.0f / 3.0f);
        sc[g] = s;
        int bin = (int)(s * 512.0f);
        bin = max(0, min(511, bin));
        atomicAdd(&hist[bin], 1);
    }
    __syncthreads();

    if (tid == 0) {
        int cum = 0, bB = 0, def = 0;
        for (int v = 511; v >= 0; v--) {
            cum += hist[v];
            if (cum >= SEL) { bB = v; def = cum - hist[v]; break; }
        }
        s_binB = bB; s_definite = def;
    }
    __syncthreads();
    int binB = s_binB;

    for (int g = tid; g < GRID_N; g += 256) {
        float s = sc[g];
        int bin = (int)(s * 512.0f);
        bin = max(0, min(511, bin));
        if (bin > binB) {
            int p = atomicAdd(&cnt_hi, 1);
            hi_idx[p] = g;                      // p < SEL guaranteed
        } else if (bin == binB) {
            int p = atomicAdd(&cnt_cb, 1);
            if (p < 512) { cb_sc[p] = s; cb_idx[p] = g; }
            else overflow = 1;
        }
    }
    __syncthreads();

    if (!overflow) {
        // threads 32..: copy definite winners
        if (tid >= 32 && (tid - 32) < s_definite) sel[tid - 32] = hi_idx[tid - 32];
        // warp 0: select remaining from critical bin (value desc, index asc tiebreak)
        if (tid < 32) {
            int need = SEL - s_definite;
            int n = min(cnt_cb, 512);
            for (int it = 0; it < need; it++) {
                float best = -1e30f; int bi = GRID_N;
                for (int c = tid; c < n; c += 32) {
                    float v = cb_sc[c]; int gi = cb_idx[c];
                    if (v > best || (v == best && gi < bi)) { best = v; bi = gi; }
                }
                #pragma unroll
                for (int o = 16; o; o >>= 1) {
                    float ov = __shfl_down_sync(0xffffffffu, best, o);
                    int   oi = __shfl_down_sync(0xffffffffu, bi, o);
                    if (ov > best || (ov == best && oi < bi)) { best = ov; bi = oi; }
                }
                bi = __shfl_sync(0xffffffffu, bi, 0);
                if (tid == 0) sel[s_definite + it] = bi;
                for (int c = tid; c < n; c += 32)
                    if (cb_idx[c] == bi) cb_sc[c] = -1e30f;
                __syncwarp();
            }
        }
    }
    __syncthreads();

    if (overflow) {
        // exact fallback: iterative extraction (rare, degenerate distributions)
        for (int it = 0; it < SEL; it++) {
            float best = -1e30f;
            int   bi = GRID_N;
            for (int g = tid; g < GRID_N; g += 256) {
                float v = sc[g];
                if (v > best) { best = v; bi = g; }
            }
            #pragma unroll
            for (int o = 16; o; o >>= 1) {
                float ov = __shfl_down_sync(0xffffffffu, best, o);
                int   oi = __shfl_down_sync(0xffffffffu, bi, o);
                if (ov > best || (ov == best && oi < bi)) { best = ov; bi = oi; }
            }
            if ((tid & 31) == 0) { rv[tid >> 5] = best; ri[tid >> 5] = bi; }
            __syncthreads();
            if (tid == 0) {
                float B = rv[0]; int BI = ri[0];
                for (int w = 1; w < 8; w++)
                    if (rv[w] > B || (rv[w] == B && ri[w] < BI)) { B = rv[w]; BI = ri[w]; }
                sel[it] = BI;
                sc[BI] = -1e30f;
            }
            __syncthreads();
        }
    }

    if (tid == 0) {
        for (int i = 1; i < SEL; i++) {          // ascending index sort
            int v = sel[i], j = i - 1;
            while (j >= 0 && sel[j] > v) { sel[j + 1] = sel[j]; j--; }
            sel[j + 1] = v;
        }
        for (int i = 0; i < SEL; i++) g_idx[b * SEL + i] = sel[i];
    }
}

// ---------------- K2: gather selected feature columns --------------------
__global__ void gather_kernel(const float* __restrict__ xfeat) {
    int row = blockIdx.x;           // b*SEL + s
    int b = row >> 5;
    int g = g_idx[row];
    const float* src = xfeat + (size_t)b * VDIM * GRID_N + g;
    float* dst = g_isel + (size_t)row * VDIM;
    for (int v = threadIdx.x; v < VDIM; v += blockDim.x)
        dst[v] = __ldg(&src[(size_t)v * GRID_N]);
}

// ---------------- K3: vis = i_sel @ W_vs + b_vs (double buffered) --------
#define KT1 32
#define NT1 (VDIM / KT1)
__global__ __launch_bounds__(128) void gemm1_kernel(const float* __restrict__ W,
                                                    const float* __restrict__ bias) {
    int b = blockIdx.y;
    int nb = blockIdx.x * 64;
    int tid = threadIdx.x;
    int tx = tid & 15, ty = tid >> 4;

    __shared__ float Xs[2][KT1 * 33];
    __shared__ __align__(16) float Ws[2][KT1 * 64];

    const float* Ab = g_isel + (size_t)b * SEL * VDIM;

    // load addressing
    int wk = tid >> 4;             // W: k = wk + i*8,  n = wn..wn+3
    int wn = (tid * 4) & 63;
    int xm = tid >> 3;             // X: m = xm + i*16, k = xk..xk+3
    int xk = (tid * 4) & 31;

    float4 rW[4], rX[2];

    // prologue: tile 0
    #pragma unroll
    for (int i = 0; i < 4; i++)
        rW[i] = *(const float4*)&W[(size_t)(wk + i * 8) * HDIM + nb + wn];
    #pragma unroll
    for (int i = 0; i < 2; i++)
        rX[i] = *(const float4*)&Ab[(size_t)(xm + i * 16) * VDIM + xk];
    #pragma unroll
    for (int i = 0; i < 4; i++)
        *(float4*)&Ws[0][(wk + i * 8) * 64 + wn] = rW[i];
    #pragma unroll
    for (int i = 0; i < 2; i++) {
        int m = xm + i * 16;
        Xs[0][(xk + 0) * 33 + m] = rX[i].x;
        Xs[0][(xk + 1) * 33 + m] = rX[i].y;
        Xs[0][(xk + 2) * 33 + m] = rX[i].z;
        Xs[0][(xk + 3) * 33 + m] = rX[i].w;
    }
    __syncthreads();

    float acc[4][4];
    #pragma unroll
    for (int i = 0; i < 4; i++)
        #pragma unroll
        for (int j = 0; j < 4; j++) acc[i][j] = 0.f;

    for (int t = 0; t < NT1; t++) {
        int cur = t & 1;
        int k0n = (t + 1) * KT1;
        if (t + 1 < NT1) {
            #pragma unroll
            for (int i = 0; i < 4; i++)
                rW[i] = *(const float4*)&W[(size_t)(k0n + wk + i * 8) * HDIM + nb + wn];
            #pragma unroll
            for (int i = 0; i < 2; i++)
                rX[i] = *(const float4*)&Ab[(size_t)(xm + i * 16) * VDIM + k0n + xk];
        }
        #pragma unroll
        for (int k = 0; k < KT1; k++) {
            float4 wv = *(const float4*)&Ws[cur][k * 64 + tx * 4];
            float x0 = Xs[cur][k * 33 + ty * 4 + 0];
            float x1 = Xs[cur][k * 33 + ty * 4 + 1];
            float x2 = Xs[cur][k * 33 + ty * 4 + 2];
            float x3 = Xs[cur][k * 33 + ty * 4 + 3];
            acc[0][0] += x0 * wv.x; acc[0][1] += x0 * wv.y; acc[0][2] += x0 * wv.z; acc[0][3] += x0 * wv.w;
            acc[1][0] += x1 * wv.x; acc[1][1] += x1 * wv.y; acc[1][2] += x1 * wv.z; acc[1][3] += x1 * wv.w;
            acc[2][0] += x2 * wv.x; acc[2][1] += x2 * wv.y; acc[2][2] += x2 * wv.z; acc[2][3] += x2 * wv.w;
            acc[3][0] += x3 * wv.x; acc[3][1] += x3 * wv.y; acc[3][2] += x3 * wv.z; acc[3][3] += x3 * wv.w;
        }
        if (t + 1 < NT1) {
            int nx = cur ^ 1;
            #pragma unroll
            for (int i = 0; i < 4; i++)
                *(float4*)&Ws[nx][(wk + i * 8) * 64 + wn] = rW[i];
            #pragma unroll
            for (int i = 0; i < 2; i++) {
                int m = xm + i * 16;
                Xs[nx][(xk + 0) * 33 + m] = rX[i].x;
                Xs[nx][(xk + 1) * 33 + m] = rX[i].y;
                Xs[nx][(xk + 2) * 33 + m] = rX[i].z;
                Xs[nx][(xk + 3) * 33 + m] = rX[i].w;
            }
        }
        __syncthreads();
    }

    #pragma unroll
    for (int i = 0; i < 4; i++) {
        int m = ty * 4 + i;
        float* C = g_vis + (size_t)(b * SEL + m) * HDIM + nb;
        #pragma unroll
        for (int j = 0; j < 4; j++)
            C[tx * 4 + j] = acc[i][j] + bias[nb + tx * 4 + j];
    }
}

// ---------------- K4: gate logits -> log_softmax weights (float4) --------
__global__ void wsoft_kernel(const float* __restrict__ tag, const float* __restrict__ pos,
                             const float* __restrict__ Wsoft, const float* __restrict__ bsoft) {
    int warp = (blockIdx.x * blockDim.x + threadIdx.x) >> 5;
    int lane = threadIdx.x & 31;
    if (warp >= BS * SEL) return;
    const float4* v = (const float4*)(g_vis + (size_t)warp * HDIM);
    const float4* t = (const float4*)(tag + (size_t)warp * HDIM);
    const float4* p = (const float4*)(pos + (size_t)warp * HDIM);
    const float4* Wq = (const float4*)Wsoft;   // [h][2] pairs, float4 = 2 h-rows
    float l0 = 0.f, l1 = 0.f;
    #pragma unroll
    for (int i = 0; i < 4; i++) {
        int h4 = lane + i * 32;
        float4 a = v[h4], c = t[h4], e = p[h4];
        float s0 = a.x + c.x + e.x, s1 = a.y + c.y + e.y;
        float s2 = a.z + c.z + e.z, s3 = a.w + c.w + e.w;
        float4 w01 = Wq[h4 * 2], w23 = Wq[h4 * 2 + 1];
        l0 += s0 * w01.x + s1 * w01.z + s2 * w23.x + s3 * w23.z;
        l1 += s0 * w01.y + s1 * w01.w + s2 * w23.y + s3 * w23.w;
    }
    #pragma unroll
    for (int o = 16; o; o >>= 1) {
        l0 += __shfl_xor_sync(0xffffffffu, l0, o);
        l1 += __shfl_xor_sync(0xffffffffu, l1, o);
    }
    if (lane == 0) {
        l0 = (l0 + bsoft[0]) / 0.03f;
        l1 = (l1 + bsoft[1]) / 0.03f;
        float m = fmaxf(l0, l1);
        float lse = m + logf(expf(l0 - m) + expf(l1 - m));
        g_w[2 * warp + 0] = l0 - lse;
        g_w[2 * warp + 1] = l1 - lse;
    }
}

// ---------------- K5: vis2 GEMM (double buffered, KT=16) -----------------
#define KT2 16
#define NT2 (HDIM / KT2)
__global__ __launch_bounds__(128) void gemm2_kernel(
    const float* __restrict__ Wvp, const float* __restrict__ bvp,
    const float* __restrict__ Wtg, const float* __restrict__ btg,
    const float* __restrict__ tag, const float* __restrict__ pos) {
    int b = blockIdx.y;
    int nb = blockIdx.x * 64;
    int tid = threadIdx.x;
    int tx = tid & 15, ty = tid >> 4;

    __shared__ float Xs[2][KT2 * 35], Ys[2][KT2 * 35];
    __shared__ __align__(16) float Ws[2][KT2 * 64];
    __shared__ __align__(16) float Vs[2][KT2 * 64];
    __shared__ float w0s[SEL], w1s[SEL];

    if (tid < SEL) {
        w0s[tid] = g_w[(b * SEL + tid) * 2 + 0];
        w1s[tid] = g_w[(b * SEL + tid) * 2 + 1];
    }
    __syncthreads();

    const float* Vb = g_vis + (size_t)b * SEL * HDIM;
    const float* Tb = tag + (size_t)b * SEL * HDIM;

    int wk = tid >> 4;             // W/V: k = wk + i*8 (i=0..1), n = wn..+3
    int wn = (tid * 4) & 63;
    int xm = tid >> 2;             // X/Y: m = xm, k = xk..+3
    int xk = (tid * 4) & 15;
    float fw0 = w0s[xm], fw1 = w1s[xm];

    float4 rW[2], rV[2], rX, rY;

    // prologue
    #pragma unroll
    for (int i = 0; i < 2; i++) {
        rW[i] = *(const float4*)&Wvp[(size_t)(wk + i * 8) * HDIM + nb + wn];
        rV[i] = *(const float4*)&Wtg[(size_t)(wk + i * 8) * HDIM + nb + wn];
    }
    rX = *(const float4*)&Vb[(size_t)xm * HDIM + xk];
    rY = *(const float4*)&Tb[(size_t)xm * HDIM + xk];
    #pragma unroll
    for (int i = 0; i < 2; i++) {
        *(float4*)&Ws[0][(wk + i * 8) * 64 + wn] = rW[i];
        *(float4*)&Vs[0][(wk + i * 8) * 64 + wn] = rV[i];
    }
    Xs[0][(xk + 0) * 35 + xm] = rX.x * fw0; Xs[0][(xk + 1) * 35 + xm] = rX.y * fw0;
    Xs[0][(xk + 2) * 35 + xm] = rX.z * fw0; Xs[0][(xk + 3) * 35 + xm] = rX.w * fw0;
    Ys[0][(xk + 0) * 35 + xm] = rY.x * fw1; Ys[0][(xk + 1) * 35 + xm] = rY.y * fw1;
    Ys[0][(xk + 2) * 35 + xm] = rY.z * fw1; Ys[0][(xk + 3) * 35 + xm] = rY.w * fw1;
    __syncthreads();

    float acc[4][4];
    #pragma unroll
    for (int i = 0; i < 4; i++)
        #pragma unroll
        for (int j = 0; j < 4; j++) acc[i][j] = 0.f;

    for (int t = 0; t < NT2; t++) {
        int cur = t & 1;
        int k0n = (t + 1) * KT2;
        if (t + 1 < NT2) {
            #pragma unroll
            for (int i = 0; i < 2; i++) {
                rW[i] = *(const float4*)&Wvp[(size_t)(k0n + wk + i * 8) * HDIM + nb + wn];
                rV[i] = *(const float4*)&Wtg[(size_t)(k0n + wk + i * 8) * HDIM + nb + wn];
            }
            rX = *(const float4*)&Vb[(size_t)xm * HDIM + k0n + xk];
            rY = *(const float4*)&Tb[(size_t)xm * HDIM + k0n + xk];
        }
        #pragma unroll
        for (int k = 0; k < KT2; k++) {
            float4 wv = *(const float4*)&Ws[cur][k * 64 + tx * 4];
            float4 vv = *(const float4*)&Vs[cur][k * 64 + tx * 4];
            float x0 = Xs[cur][k * 35 + ty * 4 + 0];
            float x1 = Xs[cur][k * 35 + ty * 4 + 1];
            float x2 = Xs[cur][k * 35 + ty * 4 + 2];
            float x3 = Xs[cur][k * 35 + ty * 4 + 3];
            float y0 = Ys[cur][k * 35 + ty * 4 + 0];
            float y1 = Ys[cur][k * 35 + ty * 4 + 1];
            float y2 = Ys[cur][k * 35 + ty * 4 + 2];
            float y3 = Ys[cur][k * 35 + ty * 4 + 3];
            acc[0][0] += x0 * wv.x + y0 * vv.x; acc[0][1] += x0 * wv.y + y0 * vv.y;
            acc[0][2] += x0 * wv.z + y0 * vv.z; acc[0][3] += x0 * wv.w + y0 * vv.w;
            acc[1][0] += x1 * wv.x + y1 * vv.x; acc[1][1] += x1 * wv.y + y1 * vv.y;
            acc[1][2] += x1 * wv.z + y1 * vv.z; acc[1][3] += x1 * wv.w + y1 * vv.w;
            acc[2][0] += x2 * wv.x + y2 * vv.x; acc[2][1] += x2 * wv.y + y2 * vv.y;
            acc[2][2] += x2 * wv.z + y2 * vv.z; acc[2][3] += x2 * wv.w + y2 * vv.w;
            acc[3][0] += x3 * wv.x + y3 * vv.x; acc[3][1] += x3 * wv.y + y3 * vv.y;
            acc[3][2] += x3 * wv.z + y3 * vv.z; acc[3][3] += x3 * wv.w + y3 * vv.w;
        }
        if (t + 1 < NT2) {
            int nx = cur ^ 1;
            #pragma unroll
            for (int i = 0; i < 2; i++) {
                *(float4*)&Ws[nx][(wk + i * 8) * 64 + wn] = rW[i];
                *(float4*)&Vs[nx][(wk + i * 8) * 64 + wn] = rV[i];
            }
            Xs[nx][(xk + 0) * 35 + xm] = rX.x * fw0; Xs[nx][(xk + 1) * 35 + xm] = rX.y * fw0;
            Xs[nx][(xk + 2) * 35 + xm] = rX.z * fw0; Xs[nx][(xk + 3) * 35 + xm] = rX.w * fw0;
            Ys[nx][(xk + 0) * 35 + xm] = rY.x * fw1; Ys[nx][(xk + 1) * 35 + xm] = rY.y * fw1;
            Ys[nx][(xk + 2) * 35 + xm] = rY.z * fw1; Ys[nx][(xk + 3) * 35 + xm] = rY.w * fw1;
        }
        __syncthreads();
    }

    #pragma unroll
    for (int i = 0; i < 4; i++) {
        int m = ty * 4 + i;
        size_t roff = (size_t)(b * SEL + m) * HDIM + nb;
        #pragma unroll
        for (int j = 0; j < 4; j++) {
            int n = tx * 4 + j;
            g_vis2[roff + n] = acc[i][j] + bvp[nb + n] + btg[nb + n] + pos[roff + n];
        }
    }
}

// ---------------- K6: language projection + norm -------------------------
__global__ void lang_kernel(const float* __restrict__ lang, const float* __restrict__ Wts,
                            const float* __restrict__ bts) {
    int b = blockIdx.x, tid = threadIdx.x;   // 256 threads
    __shared__ float lg[HDIM];
    __shared__ float red[256];
    for (int h = tid; h < HDIM; h += 256) lg[h] = lang[b * HDIM + h];
    __syncthreads();
    int h0 = tid, h1 = tid + 256;
    float a0 = bts[h0], a1 = bts[h1];
    #pragma unroll 4
    for (int k = 0; k < HDIM; k++) {
        float l = lg[k];
        a0 += l * Wts[(size_t)k * HDIM + h0];
        a1 += l * Wts[(size_t)k * HDIM + h1];
    }
    g_lang[b * HDIM + h0] = a0;
    g_lang[b * HDIM + h1] = a1;
    red[tid] = a0 * a0 + a1 * a1;
    __syncthreads();
    for (int o = 128; o; o >>= 1) { if (tid < o) red[tid] += red[tid + o]; __syncthreads(); }
    if (tid == 0) g_ln[b] = sqrtf(red[0]) + EPSF;
}

// ---------------- K7: cosine sim (warp per sel), argmax, box decode ------
__global__ void final_kernel(const float* __restrict__ boxes, float* __restrict__ out) {
    int b = blockIdx.x, tid = threadIdx.x;   // 1024 threads = 32 warps
    int w = tid >> 5, lane = tid & 31;
    __shared__ float ssim[SEL];

    const float4* v2 = (const float4*)(g_vis2 + (size_t)(b * SEL + w) * HDIM);
    const float4* le = (const float4*)(g_lang + (size_t)b * HDIM);
    float d = 0.f, q = 0.f;
    #pragma unroll
    for (int i = 0; i < 4; i++) {
        float4 a = v2[lane + i * 32];
        float4 c = le[lane + i * 32];
        d += a.x * c.x + a.y * c.y + a.z * c.z + a.w * c.w;
        q += a.x * a.x + a.y * a.y + a.z * a.z + a.w * a.w;
    }
    #pragma unroll
    for (int o = 16; o; o >>= 1) {
        d += __shfl_xor_sync(0xffffffffu, d, o);
        q += __shfl_xor_sync(0xffffffffu, q, o);
    }
    if (lane == 0) ssim[w] = d / ((sqrtf(q) + EPSF) * g_ln[b]);
    __syncthreads();

    if (tid < SEL) out[BS * 5 + b * SEL + tid] = ssim[tid];

    if (w == 0) {
        float v = ssim[lane]; int bi = lane;
        #pragma unroll
        for (int o = 16; o; o >>= 1) {
            float ov = __shfl_down_sync(0xffffffffu, v, o);
            int   oi = __shfl_down_sync(0xffffffffu, bi, o);
            if (ov > v || (ov == v && oi < bi)) { v = ov; bi = oi; }
        }
        if (lane == 0) {
            int g = g_idx[b * SEL + bi];
            const float* base = boxes + ((size_t)b * GRID_N + g) * A_N * CH;
            int j = 0; float ov = base[4];
            for (int a = 1; a < A_N; a++) {
                float o2 = base[a * CH + 4];
                if (o2 > ov) { ov = o2; j = a; }
            }
            float x = base[j * CH + 0], y = base[j * CH + 1];
            float wd = base[j * CH + 2], hh = base[j * CH + 3];
            float x1 = x - wd * 0.5f, y1 = y - hh * 0.5f;
            out[b * 5 + 0] = x1;
            out[b * 5 + 1] = y1;
            out[b * 5 + 2] = x1 + wd;
            out[b * 5 + 3] = y1 + hh;
            out[b * 5 + 4] = ov;
        }
    }
}

// ---------------- launch --------------------------------------------------
extern "C" void kernel_launch(void* const* d_in, const int* in_sizes, int n_in,
                              void* d_out, int out_size) {
    const float* boxes    = (const float*)d_in[0];
    const float* x_feat   = (const float*)d_in[1];
    const float* tag_emb  = (const float*)d_in[2];
    const float* pos_emb  = (const float*)d_in[3];
    const float* lang     = (const float*)d_in[4];
    const float* W_vs     = (const float*)d_in[5];
    const float* b_vs     = (const float*)d_in[6];
    const float* W_ts     = (const float*)d_in[7];
    const float* b_ts     = (const float*)d_in[8];
    const float* W_vs_pos = (const float*)d_in[9];
    const float* b_vs_pos = (const float*)d_in[10];
    const float* W_tag    = (const float*)d_in[11];
    const float* b_tag    = (const float*)d_in[12];
    const float* W_soft   = (const float*)d_in[13];
    const float* b_soft   = (const float*)d_in[14];
    float* out = (float*)d_out;

    topk_kernel<<<BS, 256>>>(boxes);
    gather_kernel<<<BS * SEL, 256>>>(x_feat);
    lang_kernel<<<BS, 256>>>(lang, W_ts, b_ts);
    gemm1_kernel<<<dim3(HDIM / 64, BS), 128>>>(W_vs, b_vs);
    wsoft_kernel<<<(BS * SEL * 32 + 255) / 256, 256>>>(tag_emb, pos_emb, W_soft, b_soft);
    gemm2_kernel<<<dim3(HDIM / 64, BS), 128>>>(W_vs_pos, b_vs_pos, W_tag, b_tag, tag_emb, pos_emb);
    final_kernel<<<BS, 1024>>>(boxes, out);
}